// round 7
// baseline (speedup 1.0000x reference)
#include <cuda_runtime.h>
#include <cstdint>

#define B_ 2048
#define S_ 64
#define D_ 512
#define N_ 64
#define A_ 64
#define F_ 512

typedef unsigned long long u64;

// ---------------- persistent device scratch ------------------------------------
__device__ __align__(16) float g_k[N_ * F_];
__device__ __align__(16) float g_kq[N_ * D_];
__device__ __align__(16) float g_M1[A_ * F_];
__device__ __align__(16) float g_c1[F_];
__device__ __align__(16) float g_c2[F_];
__device__ __align__(16) float g_c3[F_];
__device__ __align__(16) float g_G2[A_ * A_];
__device__ __align__(16) float g_wb[A_];
__device__ __align__(16) float g_wsum[A_];
__device__ __align__(16) float g_scal[2];
__device__ __align__(16) float g_attnE2[(size_t)B_ * N_ * S_ * 2];  // dup pairs, 64MB

// ---------------- f32x2 helpers --------------------------------------------------
__device__ __forceinline__ u64 fma2(u64 a, u64 b, u64 c) {
    u64 d;
    asm("fma.rn.f32x2 %0, %1, %2, %3;" : "=l"(d) : "l"(a), "l"(b), "l"(c));
    return d;
}
__device__ __forceinline__ u64 dup2(float v) {
    u64 d;
    asm("mov.b64 %0, {%1, %1};" : "=l"(d) : "f"(v));
    return d;
}
__device__ __forceinline__ float2 unpk(u64 v) {
    float2 r;
    asm("mov.b64 {%0, %1}, %2;" : "=f"(r.x), "=f"(r.y) : "l"(v));
    return r;
}

// ---------------- setup: everything except kq, from raw inputs --------------------
// blocks 0..63   : M1[b][t]  = sum_f W_ae[f][b] * ln_g[f] * Wv[t][f]
// block  64      : c1[t], c2[t], c3[t]
// blocks 65..72  : G2[al][be] = sum_f W_ae[f][al] * W_ae[f][be]
// block  73      : wb, wsum, scal
// blocks 74..137 : k[n][g] = sum_f (W_ie[f][n] + b_ie[f]) * Wk[g][f]
__global__ __launch_bounds__(512)
void setup_master(const float* __restrict__ W_ae, const float* __restrict__ b_ae,
                  const float* __restrict__ W_ie, const float* __restrict__ b_ie,
                  const float* __restrict__ ln_g, const float* __restrict__ ln_b,
                  const float* __restrict__ Wk, const float* __restrict__ Wv) {
    const int t = threadIdx.x;
    const int b = blockIdx.x;
    if (b < 64) {
        float a0 = 0.f, a1 = 0.f, a2 = 0.f, a3 = 0.f;
        for (int f = 0; f < F_; f += 4) {
            float4 wv = *(const float4*)&Wv[t * 512 + f];
            float4 lg = *(const float4*)&ln_g[f];
            a0 += W_ae[(f + 0) * A_ + b] * lg.x * wv.x;
            a1 += W_ae[(f + 1) * A_ + b] * lg.y * wv.y;
            a2 += W_ae[(f + 2) * A_ + b] * lg.z * wv.z;
            a3 += W_ae[(f + 3) * A_ + b] * lg.w * wv.w;
        }
        g_M1[b * 512 + t] = (a0 + a1) + (a2 + a3);
    } else if (b == 64) {
        float c1 = 0.f, c2 = 0.f, c3 = 0.f;
        for (int f = 0; f < F_; f += 2) {
            float2 wv = *(const float2*)&Wv[t * 512 + f];
            c1 += b_ae[f] * ln_g[f] * wv.x + b_ae[f + 1] * ln_g[f + 1] * wv.y;
            c2 += ln_g[f] * wv.x + ln_g[f + 1] * wv.y;
            c3 += ln_b[f] * wv.x + ln_b[f + 1] * wv.y;
        }
        g_c1[t] = c1; g_c2[t] = c2; g_c3[t] = c3;
    } else if (b < 73) {
        int idx = (b - 65) * 512 + t;
        int al = idx & 63, be = idx >> 6;
        float a0 = 0.f, a1 = 0.f, a2 = 0.f, a3 = 0.f;
#pragma unroll 4
        for (int f = 0; f < F_; f += 4) {
            a0 += W_ae[(f + 0) * A_ + al] * W_ae[(f + 0) * A_ + be];
            a1 += W_ae[(f + 1) * A_ + al] * W_ae[(f + 1) * A_ + be];
            a2 += W_ae[(f + 2) * A_ + al] * W_ae[(f + 2) * A_ + be];
            a3 += W_ae[(f + 3) * A_ + al] * W_ae[(f + 3) * A_ + be];
        }
        g_G2[al * A_ + be] = (a0 + a1) + (a2 + a3);
    } else if (b == 73) {
        if (t < 64) {
            float aw = 0.f, as = 0.f;
#pragma unroll 4
            for (int f = 0; f < F_; f++) {
                float w = W_ae[f * A_ + t];
                aw += w * b_ae[f];
                as += w;
            }
            g_wb[t] = aw;
            g_wsum[t] = as;
        } else if (t == 64) {
            float bb = 0.f, sb = 0.f;
            for (int f = 0; f < F_; f++) {
                float v = b_ae[f];
                bb += v * v;
                sb += v;
            }
            g_scal[0] = bb;
            g_scal[1] = sb;
        }
    } else {
        int idx = (b - 74) * 512 + t;
        int n = idx & 63;
        int g = idx >> 6;
        float a0 = 0.f, a1 = 0.f, a2 = 0.f, a3 = 0.f;
#pragma unroll 4
        for (int f = 0; f < F_; f += 4) {
            a0 += (W_ie[(f + 0) * N_ + n] + b_ie[f + 0]) * Wk[g * F_ + f + 0];
            a1 += (W_ie[(f + 1) * N_ + n] + b_ie[f + 1]) * Wk[g * F_ + f + 1];
            a2 += (W_ie[(f + 2) * N_ + n] + b_ie[f + 2]) * Wk[g * F_ + f + 2];
            a3 += (W_ie[(f + 3) * N_ + n] + b_ie[f + 3]) * Wk[g * F_ + f + 3];
        }
        g_k[n * F_ + g] = (a0 + a1) + (a2 + a3);
    }
}

// ---------------- setup 2: kq = scale * k @ Wq  (grid 8x8, 64 thr) ---------------
__global__ void setup_kq(const float* __restrict__ Wq) {
    int d = blockIdx.y * 64 + threadIdx.x;
    int n0 = blockIdx.x * 8;
    float acc[8];
#pragma unroll
    for (int j = 0; j < 8; j++) acc[j] = 0.f;
#pragma unroll 4
    for (int f = 0; f < F_; f++) {
        float wq = Wq[f * D_ + d];
#pragma unroll
        for (int j = 0; j < 8; j++)
            acc[j] += g_k[(n0 + j) * F_ + f] * wq;
    }
    const float scale = 0.04419417382415922f;  // 512^-0.5
#pragma unroll
    for (int j = 0; j < 8; j++)
        g_kq[(n0 + j) * D_ + d] = acc[j] * scale;
}

// =================== kernel A: logits + softmax -> attn, attnE2 ==================
__global__ __launch_bounds__(256, 3)
void attn_kernel(const float* __restrict__ slots, float* __restrict__ out_attn) {
    __shared__ float2 sKq2[64 * 64];    // [n][d-chunk] dup pairs, 32KB
    __shared__ float  sSlT[64 * 68];    // [d][s] transposed chunk, 17.4KB
    const int t = threadIdx.x;
    const int b = blockIdx.x;
    const float* slots_b = slots + (size_t)b * S_ * D_;
    const int nI = t >> 3, sI = t & 7;
    const int n0 = nI * 2, s0 = sI * 8;

    u64 acc[2][4];
#pragma unroll
    for (int i = 0; i < 2; i++)
#pragma unroll
        for (int j = 0; j < 4; j++) acc[i][j] = 0ull;

    for (int dc = 0; dc < 8; dc++) {
        if (dc) __syncthreads();
#pragma unroll
        for (int j = 0; j < 16; j++) {
            int i = t + j * 256;
            int n = i >> 6, d = i & 63;
            float v = g_kq[n * 512 + dc * 64 + d];
            sKq2[n * 64 + d] = make_float2(v, v);
        }
#pragma unroll
        for (int j = 0; j < 4; j++) {
            int i = t + j * 256;
            int s = i >> 4, q = i & 15;
            float4 v = *(const float4*)&slots_b[s * 512 + dc * 64 + q * 4];
            sSlT[(q * 4 + 0) * 68 + s] = v.x;
            sSlT[(q * 4 + 1) * 68 + s] = v.y;
            sSlT[(q * 4 + 2) * 68 + s] = v.z;
            sSlT[(q * 4 + 3) * 68 + s] = v.w;
        }
        __syncthreads();

        const ulonglong2* kq0 = (const ulonglong2*)&sKq2[n0 * 64];
        const ulonglong2* kq1 = (const ulonglong2*)&sKq2[(n0 + 1) * 64];
#pragma unroll
        for (int d2 = 0; d2 < 32; d2++) {
            ulonglong2 k0 = kq0[d2];
            ulonglong2 k1 = kq1[d2];
            ulonglong2 sa = *(const ulonglong2*)&sSlT[(2 * d2) * 68 + s0];
            ulonglong2 sb = *(const ulonglong2*)&sSlT[(2 * d2) * 68 + s0 + 4];
            ulonglong2 sc = *(const ulonglong2*)&sSlT[(2 * d2 + 1) * 68 + s0];
            ulonglong2 sd = *(const ulonglong2*)&sSlT[(2 * d2 + 1) * 68 + s0 + 4];
            acc[0][0] = fma2(k0.x, sa.x, acc[0][0]);
            acc[0][1] = fma2(k0.x, sa.y, acc[0][1]);
            acc[0][2] = fma2(k0.x, sb.x, acc[0][2]);
            acc[0][3] = fma2(k0.x, sb.y, acc[0][3]);
            acc[1][0] = fma2(k1.x, sa.x, acc[1][0]);
            acc[1][1] = fma2(k1.x, sa.y, acc[1][1]);
            acc[1][2] = fma2(k1.x, sb.x, acc[1][2]);
            acc[1][3] = fma2(k1.x, sb.y, acc[1][3]);
            acc[0][0] = fma2(k0.y, sc.x, acc[0][0]);
            acc[0][1] = fma2(k0.y, sc.y, acc[0][1]);
            acc[0][2] = fma2(k0.y, sd.x, acc[0][2]);
            acc[0][3] = fma2(k0.y, sd.y, acc[0][3]);
            acc[1][0] = fma2(k1.y, sc.x, acc[1][0]);
            acc[1][1] = fma2(k1.y, sc.y, acc[1][1]);
            acc[1][2] = fma2(k1.y, sd.x, acc[1][2]);
            acc[1][3] = fma2(k1.y, sd.y, acc[1][3]);
        }
    }

    // register softmax across the 8 lanes sharing each n-row (lanes sI=0..7)
    float* o2 = out_attn + (size_t)b * N_ * S_;
    float* gE = g_attnE2 + (size_t)b * 8192;
#pragma unroll
    for (int i = 0; i < 2; i++) {
        float l[8];
#pragma unroll
        for (int j = 0; j < 4; j++) {
            float2 p = unpk(acc[i][j]);
            l[2 * j] = p.x;
            l[2 * j + 1] = p.y;
        }
        float m = l[0];
#pragma unroll
        for (int j = 1; j < 8; j++) m = fmaxf(m, l[j]);
#pragma unroll
        for (int o = 1; o < 8; o <<= 1) m = fmaxf(m, __shfl_xor_sync(0xffffffffu, m, o));
        float sum = 0.f;
#pragma unroll
        for (int j = 0; j < 8; j++) {
            l[j] = __expf(l[j] - m);
            sum += l[j];
        }
#pragma unroll
        for (int o = 1; o < 8; o <<= 1) sum += __shfl_xor_sync(0xffffffffu, sum, o);
        float inv = 1.f / sum;
#pragma unroll
        for (int j = 0; j < 8; j++) l[j] *= inv;

        int n = n0 + i;
        *(float4*)&o2[n * 64 + s0]     = make_float4(l[0], l[1], l[2], l[3]);
        *(float4*)&o2[n * 64 + s0 + 4] = make_float4(l[4], l[5], l[6], l[7]);
        float e0 = l[0] + 1e-8f, e1 = l[1] + 1e-8f, e2v = l[2] + 1e-8f, e3 = l[3] + 1e-8f;
        float e4 = l[4] + 1e-8f, e5 = l[5] + 1e-8f, e6 = l[6] + 1e-8f, e7 = l[7] + 1e-8f;
        float4* gd = (float4*)&gE[n * 128 + s0 * 2];
        gd[0] = make_float4(e0, e0, e1, e1);
        gd[1] = make_float4(e2v, e2v, e3, e3);
        gd[2] = make_float4(e4, e4, e5, e5);
        gd[3] = make_float4(e6, e6, e7, e7);
    }
}

// =================== kernel B: stats + P + T (per f-half) ========================
// grid (2048, 2). smem: sV 64KB | sAct2 dup 33.8KB (aliased by sE 32KB in T) | stats
#define BSM_FLOATS (64 * 256 + 64 * 66 * 2 + 128)
__global__ __launch_bounds__(256, 2)
void bind_kernel(const float* __restrict__ actions,
                 float* __restrict__ out_slots) {
    extern __shared__ float bsm[];
    float*  sV     = bsm;                           // 64 x 256
    float2* sAct2  = (float2*)(bsm + 64 * 256);     // 64 x 66 dup pairs
    float*  sE     = bsm + 64 * 256;                // alias (T phase, 8192 floats)
    float*  sStats = bsm + 64 * 256 + 64 * 66 * 2;  // 128

    const int t = threadIdx.x;
    const int b = blockIdx.x;
    const int fy = blockIdx.y;
    const float* act_b = actions + (size_t)b * N_ * A_;

#pragma unroll
    for (int j = 0; j < 16; j++) {
        int i = t + j * 256;
        int n = i >> 6, al = i & 63;
        float v = act_b[i];
        sAct2[n * 66 + al] = make_float2(v, v);
    }
    __syncthreads();

    // ---- LN stats per n (closed form; G2/wb/wsum from L2-resident globals) ----
    {
        const int n = t >> 2, seg = t & 3;     // 16 beta cols per thread
        float dotj[16];
#pragma unroll
        for (int j = 0; j < 16; j++) dotj[j] = 0.f;
        for (int al = 0; al < 64; al++) {
            float av = sAct2[n * 66 + al].x;
            const float4* g4 = (const float4*)&g_G2[al * 64 + seg * 16];
#pragma unroll
            for (int q = 0; q < 4; q++) {
                float4 g = g4[q];
                dotj[q * 4 + 0] += av * g.x;
                dotj[q * 4 + 1] += av * g.y;
                dotj[q * 4 + 2] += av * g.z;
                dotj[q * 4 + 3] += av * g.w;
            }
        }
        float quad = 0.f, wbp = 0.f, wsp = 0.f;
#pragma unroll
        for (int j = 0; j < 16; j++) {
            int be = seg * 16 + j;
            float ab = sAct2[n * 66 + be].x;
            quad += ab * dotj[j];
            wbp += ab * g_wb[be];
            wsp += ab * g_wsum[be];
        }
#pragma unroll
        for (int o = 1; o < 4; o <<= 1) {
            quad += __shfl_xor_sync(0xffffffffu, quad, o);
            wbp  += __shfl_xor_sync(0xffffffffu, wbp, o);
            wsp  += __shfl_xor_sync(0xffffffffu, wsp, o);
        }
        if (seg == 0) {
            float bb = g_scal[0], sb = g_scal[1];
            float mu = (wsp + sb) * (1.f / 512.f);
            float e2 = (quad + 2.f * wbp + bb) * (1.f / 512.f);
            float var = e2 - mu * mu;
            sStats[2 * n]     = mu;
            sStats[2 * n + 1] = rsqrtf(var + 1e-5f);
        }
    }
    __syncthreads();

    // ---- Phase P: v[n][f-pair] into sV ----
    {
        const int fp = t & 127, ng = t >> 7;
        const int n0 = ng * 32;
        const int fbase = fy * 256 + fp * 2;
        u64 acc[32];
        u64 c1p = *(const u64*)&g_c1[fbase];
#pragma unroll
        for (int n = 0; n < 32; n++) acc[n] = c1p;

        for (int al2 = 0; al2 < 32; al2++) {
            u64 w0 = *(const u64*)&g_M1[(2 * al2) * 512 + fbase];
            u64 w1 = *(const u64*)&g_M1[(2 * al2 + 1) * 512 + fbase];
#pragma unroll
            for (int n4 = 0; n4 < 8; n4++) {
                ulonglong2 a0 = *(const ulonglong2*)&sAct2[(n0 + n4 * 4 + 0) * 66 + 2 * al2];
                ulonglong2 a1 = *(const ulonglong2*)&sAct2[(n0 + n4 * 4 + 1) * 66 + 2 * al2];
                ulonglong2 a2 = *(const ulonglong2*)&sAct2[(n0 + n4 * 4 + 2) * 66 + 2 * al2];
                ulonglong2 a3 = *(const ulonglong2*)&sAct2[(n0 + n4 * 4 + 3) * 66 + 2 * al2];
                acc[n4 * 4 + 0] = fma2(a0.x, w0, acc[n4 * 4 + 0]);
                acc[n4 * 4 + 1] = fma2(a1.x, w0, acc[n4 * 4 + 1]);
                acc[n4 * 4 + 2] = fma2(a2.x, w0, acc[n4 * 4 + 2]);
                acc[n4 * 4 + 3] = fma2(a3.x, w0, acc[n4 * 4 + 3]);
                acc[n4 * 4 + 0] = fma2(a0.y, w1, acc[n4 * 4 + 0]);
                acc[n4 * 4 + 1] = fma2(a1.y, w1, acc[n4 * 4 + 1]);
                acc[n4 * 4 + 2] = fma2(a2.y, w1, acc[n4 * 4 + 2]);
                acc[n4 * 4 + 3] = fma2(a3.y, w1, acc[n4 * 4 + 3]);
            }
        }
        u64 c2p = *(const u64*)&g_c2[fbase];
        u64 c3p = *(const u64*)&g_c3[fbase];
#pragma unroll
        for (int n = 0; n < 32; n++) {
            float mu = sStats[2 * (n0 + n)], rs = sStats[2 * (n0 + n) + 1];
            u64 v = fma2(dup2(rs), acc[n], fma2(dup2(-rs * mu), c2p, c3p));
            *(u64*)&sV[(n0 + n) * 256 + fp * 2] = v;
        }
    }
    __syncthreads();

    // ---- stage all of E (dup pairs) into the dead act region ----
    {
        const float4* gE4 = (const float4*)(g_attnE2 + (size_t)b * 8192);
        float4* sE4 = (float4*)sE;
#pragma unroll
        for (int j = 0; j < 8; j++)
            sE4[t + j * 256] = gE4[t + j * 256];
    }
    __syncthreads();

    // ---- Phase T (barrier-free): out[s][f-pair] = sum_n eDup(n,s) * vPair(n,f)
    {
        const int fp = t & 127;          // f-pair within the 256-col window
        const int sg = t >> 7;           // s half: 0 -> s 0..31, 1 -> s 32..63
        u64 tacc[32];
#pragma unroll
        for (int i = 0; i < 32; i++) tacc[i] = 0ull;

        for (int n = 0; n < 64; n++) {
            u64 vp = *(const u64*)&sV[n * 256 + 2 * fp];
            const ulonglong2* ap = (const ulonglong2*)(sE + n * 128 + sg * 64);
#pragma unroll
            for (int j = 0; j < 16; j++) {
                ulonglong2 a = ap[j];     // dup(e_{2j}), dup(e_{2j+1})
                tacc[2 * j]     = fma2(a.x, vp, tacc[2 * j]);
                tacc[2 * j + 1] = fma2(a.y, vp, tacc[2 * j + 1]);
            }
        }
        float* o1 = out_slots + (size_t)b * S_ * F_ + fy * 256;
#pragma unroll
        for (int sl = 0; sl < 32; sl++) {
            int s = sg * 32 + sl;
            float2 p = unpk(tacc[sl]);
            *(float2*)&o1[s * 512 + 2 * fp] = p;
        }
    }
}

// ---------------- launch ----------------------------------------------------------
extern "C" void kernel_launch(void* const* d_in, const int* in_sizes, int n_in,
                              void* d_out, int out_size) {
    const float* slots   = (const float*)d_in[0];
    const float* actions = (const float*)d_in[1];
    const float* W_ae    = (const float*)d_in[2];
    const float* b_ae    = (const float*)d_in[3];
    const float* W_ie    = (const float*)d_in[4];
    const float* b_ie    = (const float*)d_in[5];
    const float* ln_g    = (const float*)d_in[6];
    const float* ln_b    = (const float*)d_in[7];
    const float* Wq      = (const float*)d_in[8];
    const float* Wk      = (const float*)d_in[9];
    const float* Wv      = (const float*)d_in[10];

    float* out      = (float*)d_out;
    float* out_attn = out + (size_t)B_ * S_ * F_;

    setup_master<<<138, 512>>>(W_ae, b_ae, W_ie, b_ie, ln_g, ln_b, Wk, Wv);
    setup_kq<<<dim3(8, 8), 64>>>(Wq);
    attn_kernel<<<B_, 256>>>(slots, out_attn);

    const size_t BSM = BSM_FLOATS * sizeof(float);
    cudaFuncSetAttribute(bind_kernel,
                         cudaFuncAttributeMaxDynamicSharedMemorySize, (int)BSM);
    bind_kernel<<<dim3(B_, 2), 256, BSM>>>(actions, out);
}

// round 8
// speedup vs baseline: 1.2103x; 1.2103x over previous
#include <cuda_runtime.h>
#include <cstdint>

#define B_ 2048
#define S_ 64
#define D_ 512
#define N_ 64
#define A_ 64
#define F_ 512

typedef unsigned long long u64;

// ---------------- persistent device scratch ------------------------------------
__device__ __align__(16) float g_k[N_ * F_];
__device__ __align__(16) float g_kq[N_ * D_];
__device__ __align__(16) float g_M1[A_ * F_];
__device__ __align__(16) float g_c1[F_];
__device__ __align__(16) float g_c2[F_];
__device__ __align__(16) float g_c3[F_];
__device__ __align__(16) float g_G2[A_ * A_];
__device__ __align__(16) float g_wb[A_];
__device__ __align__(16) float g_wsum[A_];
__device__ __align__(16) float g_scal[2];
__device__ __align__(16) float g_attnE2[(size_t)B_ * N_ * S_ * 2];  // dup pairs

// ---------------- f32x2 helpers --------------------------------------------------
__device__ __forceinline__ u64 fma2(u64 a, u64 b, u64 c) {
    u64 d;
    asm("fma.rn.f32x2 %0, %1, %2, %3;" : "=l"(d) : "l"(a), "l"(b), "l"(c));
    return d;
}
__device__ __forceinline__ u64 dup2(float v) {
    u64 d;
    asm("mov.b64 %0, {%1, %1};" : "=l"(d) : "f"(v));
    return d;
}
__device__ __forceinline__ float2 unpk(u64 v) {
    float2 r;
    asm("mov.b64 {%0, %1}, %2;" : "=f"(r.x), "=f"(r.y) : "l"(v));
    return r;
}

// ---------------- setup: everything except kq, from raw inputs --------------------
__global__ __launch_bounds__(512)
void setup_master(const float* __restrict__ W_ae, const float* __restrict__ b_ae,
                  const float* __restrict__ W_ie, const float* __restrict__ b_ie,
                  const float* __restrict__ ln_g, const float* __restrict__ ln_b,
                  const float* __restrict__ Wk, const float* __restrict__ Wv) {
    const int t = threadIdx.x;
    const int b = blockIdx.x;
    if (b < 64) {
        float a0 = 0.f, a1 = 0.f, a2 = 0.f, a3 = 0.f;
        for (int f = 0; f < F_; f += 4) {
            float4 wv = *(const float4*)&Wv[t * 512 + f];
            float4 lg = *(const float4*)&ln_g[f];
            a0 += W_ae[(f + 0) * A_ + b] * lg.x * wv.x;
            a1 += W_ae[(f + 1) * A_ + b] * lg.y * wv.y;
            a2 += W_ae[(f + 2) * A_ + b] * lg.z * wv.z;
            a3 += W_ae[(f + 3) * A_ + b] * lg.w * wv.w;
        }
        g_M1[b * 512 + t] = (a0 + a1) + (a2 + a3);
    } else if (b == 64) {
        float c1 = 0.f, c2 = 0.f, c3 = 0.f;
        for (int f = 0; f < F_; f += 2) {
            float2 wv = *(const float2*)&Wv[t * 512 + f];
            c1 += b_ae[f] * ln_g[f] * wv.x + b_ae[f + 1] * ln_g[f + 1] * wv.y;
            c2 += ln_g[f] * wv.x + ln_g[f + 1] * wv.y;
            c3 += ln_b[f] * wv.x + ln_b[f + 1] * wv.y;
        }
        g_c1[t] = c1; g_c2[t] = c2; g_c3[t] = c3;
    } else if (b < 73) {
        int idx = (b - 65) * 512 + t;
        int al = idx & 63, be = idx >> 6;
        float a0 = 0.f, a1 = 0.f, a2 = 0.f, a3 = 0.f;
#pragma unroll 4
        for (int f = 0; f < F_; f += 4) {
            a0 += W_ae[(f + 0) * A_ + al] * W_ae[(f + 0) * A_ + be];
            a1 += W_ae[(f + 1) * A_ + al] * W_ae[(f + 1) * A_ + be];
            a2 += W_ae[(f + 2) * A_ + al] * W_ae[(f + 2) * A_ + be];
            a3 += W_ae[(f + 3) * A_ + al] * W_ae[(f + 3) * A_ + be];
        }
        g_G2[al * A_ + be] = (a0 + a1) + (a2 + a3);
    } else if (b == 73) {
        if (t < 64) {
            float aw = 0.f, as = 0.f;
#pragma unroll 4
            for (int f = 0; f < F_; f++) {
                float w = W_ae[f * A_ + t];
                aw += w * b_ae[f];
                as += w;
            }
            g_wb[t] = aw;
            g_wsum[t] = as;
        } else if (t == 64) {
            float bb = 0.f, sb = 0.f;
            for (int f = 0; f < F_; f++) {
                float v = b_ae[f];
                bb += v * v;
                sb += v;
            }
            g_scal[0] = bb;
            g_scal[1] = sb;
        }
    } else {
        int idx = (b - 74) * 512 + t;
        int n = idx & 63;
        int g = idx >> 6;
        float a0 = 0.f, a1 = 0.f, a2 = 0.f, a3 = 0.f;
#pragma unroll 4
        for (int f = 0; f < F_; f += 4) {
            a0 += (W_ie[(f + 0) * N_ + n] + b_ie[f + 0]) * Wk[g * F_ + f + 0];
            a1 += (W_ie[(f + 1) * N_ + n] + b_ie[f + 1]) * Wk[g * F_ + f + 1];
            a2 += (W_ie[(f + 2) * N_ + n] + b_ie[f + 2]) * Wk[g * F_ + f + 2];
            a3 += (W_ie[(f + 3) * N_ + n] + b_ie[f + 3]) * Wk[g * F_ + f + 3];
        }
        g_k[n * F_ + g] = (a0 + a1) + (a2 + a3);
    }
}

// ---------------- setup 2: kq = scale * k @ Wq  (grid 8x8, 64 thr) ---------------
__global__ void setup_kq(const float* __restrict__ Wq) {
    int d = blockIdx.y * 64 + threadIdx.x;
    int n0 = blockIdx.x * 8;
    float acc[8];
#pragma unroll
    for (int j = 0; j < 8; j++) acc[j] = 0.f;
#pragma unroll 4
    for (int f = 0; f < F_; f++) {
        float wq = Wq[f * D_ + d];
#pragma unroll
        for (int j = 0; j < 8; j++)
            acc[j] += g_k[(n0 + j) * F_ + f] * wq;
    }
    const float scale = 0.04419417382415922f;  // 512^-0.5
#pragma unroll
    for (int j = 0; j < 8; j++)
        g_kq[(n0 + j) * D_ + d] = acc[j] * scale;
}

// =================== kernel A v2: logits + softmax ===============================
// 128 threads: nI = t>>3 (16 groups of 4 n), sI = t&7 (8 groups of 8 s).
// smem: sKqD [64 d][66 n] dup float2 (33.8KB) + sSlT [64 d][68 s] float (17.4KB)
#define ASM_BYTES (64 * 66 * 8 + 64 * 68 * 4)
__global__ __launch_bounds__(128, 4)
void attn_kernel(const float* __restrict__ slots, float* __restrict__ out_attn) {
    extern __shared__ char asmem[];
    float2* sKqD = (float2*)asmem;                 // [d][66]
    float*  sSlT = (float*)(asmem + 64 * 66 * 8);  // [d][68]
    const int t = threadIdx.x;
    const int b = blockIdx.x;
    const float* slots_b = slots + (size_t)b * S_ * D_;
    const int nI = t >> 3, sI = t & 7;

    u64 acc[4][4];
#pragma unroll
    for (int i = 0; i < 4; i++)
#pragma unroll
        for (int p = 0; p < 4; p++) acc[i][p] = 0ull;

    for (int dc = 0; dc < 8; dc++) {
        if (dc) __syncthreads();
        // stage kq chunk transposed + dup: sKqD[d][n]
#pragma unroll
        for (int j = 0; j < 8; j++) {
            int idx = t + j * 128;          // 1024 float4 reads
            int n = idx >> 4, dq = idx & 15;
            float4 v = *(const float4*)&g_kq[n * 512 + dc * 64 + dq * 4];
            sKqD[(dq * 4 + 0) * 66 + n] = make_float2(v.x, v.x);
            sKqD[(dq * 4 + 1) * 66 + n] = make_float2(v.y, v.y);
            sKqD[(dq * 4 + 2) * 66 + n] = make_float2(v.z, v.z);
            sKqD[(dq * 4 + 3) * 66 + n] = make_float2(v.w, v.w);
        }
        // stage slots chunk transposed: sSlT[d][s]
#pragma unroll
        for (int j = 0; j < 8; j++) {
            int idx = t + j * 128;
            int s = idx >> 4, q = idx & 15;
            float4 v = *(const float4*)&slots_b[s * 512 + dc * 64 + q * 4];
            sSlT[(q * 4 + 0) * 68 + s] = v.x;
            sSlT[(q * 4 + 1) * 68 + s] = v.y;
            sSlT[(q * 4 + 2) * 68 + s] = v.z;
            sSlT[(q * 4 + 3) * 68 + s] = v.w;
        }
        __syncthreads();

#pragma unroll 4
        for (int d = 0; d < 64; d++) {
            ulonglong2 kA = *(const ulonglong2*)&sKqD[d * 66 + 4 * nI];      // n0,n1
            ulonglong2 kB = *(const ulonglong2*)&sKqD[d * 66 + 4 * nI + 2];  // n2,n3
            ulonglong2 s01 = *(const ulonglong2*)&sSlT[d * 68 + 8 * sI];     // s pairs 0,1
            ulonglong2 s23 = *(const ulonglong2*)&sSlT[d * 68 + 8 * sI + 4]; // s pairs 2,3
            acc[0][0] = fma2(kA.x, s01.x, acc[0][0]);
            acc[0][1] = fma2(kA.x, s01.y, acc[0][1]);
            acc[0][2] = fma2(kA.x, s23.x, acc[0][2]);
            acc[0][3] = fma2(kA.x, s23.y, acc[0][3]);
            acc[1][0] = fma2(kA.y, s01.x, acc[1][0]);
            acc[1][1] = fma2(kA.y, s01.y, acc[1][1]);
            acc[1][2] = fma2(kA.y, s23.x, acc[1][2]);
            acc[1][3] = fma2(kA.y, s23.y, acc[1][3]);
            acc[2][0] = fma2(kB.x, s01.x, acc[2][0]);
            acc[2][1] = fma2(kB.x, s01.y, acc[2][1]);
            acc[2][2] = fma2(kB.x, s23.x, acc[2][2]);
            acc[2][3] = fma2(kB.x, s23.y, acc[2][3]);
            acc[3][0] = fma2(kB.y, s01.x, acc[3][0]);
            acc[3][1] = fma2(kB.y, s01.y, acc[3][1]);
            acc[3][2] = fma2(kB.y, s23.x, acc[3][2]);
            acc[3][3] = fma2(kB.y, s23.y, acc[3][3]);
        }
    }

    // register softmax: 8 lanes (sI) per n-row
    float* o2 = out_attn + (size_t)b * N_ * S_;
    float* gE = g_attnE2 + (size_t)b * 8192;
#pragma unroll
    for (int i = 0; i < 4; i++) {
        float l[8];
#pragma unroll
        for (int p = 0; p < 4; p++) {
            float2 q = unpk(acc[i][p]);
            l[2 * p] = q.x;
            l[2 * p + 1] = q.y;
        }
        float m = l[0];
#pragma unroll
        for (int j = 1; j < 8; j++) m = fmaxf(m, l[j]);
#pragma unroll
        for (int o = 1; o < 8; o <<= 1) m = fmaxf(m, __shfl_xor_sync(0xffffffffu, m, o));
        float sum = 0.f;
#pragma unroll
        for (int j = 0; j < 8; j++) {
            l[j] = __expf(l[j] - m);
            sum += l[j];
        }
#pragma unroll
        for (int o = 1; o < 8; o <<= 1) sum += __shfl_xor_sync(0xffffffffu, sum, o);
        float inv = 1.f / sum;
#pragma unroll
        for (int j = 0; j < 8; j++) l[j] *= inv;

        int n = nI * 4 + i;
        *(float4*)&o2[n * 64 + sI * 8]     = make_float4(l[0], l[1], l[2], l[3]);
        *(float4*)&o2[n * 64 + sI * 8 + 4] = make_float4(l[4], l[5], l[6], l[7]);
        float4* gd = (float4*)&gE[n * 128 + sI * 16];
        gd[0] = make_float4(l[0] + 1e-8f, l[0] + 1e-8f, l[1] + 1e-8f, l[1] + 1e-8f);
        gd[1] = make_float4(l[2] + 1e-8f, l[2] + 1e-8f, l[3] + 1e-8f, l[3] + 1e-8f);
        gd[2] = make_float4(l[4] + 1e-8f, l[4] + 1e-8f, l[5] + 1e-8f, l[5] + 1e-8f);
        gd[3] = make_float4(l[6] + 1e-8f, l[6] + 1e-8f, l[7] + 1e-8f, l[7] + 1e-8f);
    }
}

// =================== kernel B v2: stats + P + T ===================================
// 256 threads, grid (2048, 2). warp w = t>>5, lane l = t&31 → f cols 8l..8l+7.
// smem: sV [64 n][256 f] 64KB | sActT2 [al][66 n] dup float2 33.8KB (aliased by sE
//       32KB in T) | sStats 128 floats
#define BSM_BYTES (64 * 256 * 4 + 64 * 66 * 8 + 512)
__global__ __launch_bounds__(256, 2)
void bind_kernel(const float* __restrict__ actions,
                 float* __restrict__ out_slots) {
    extern __shared__ char bsmem[];
    float*  sV     = (float*)bsmem;                         // [n][256]
    float2* sActT2 = (float2*)(bsmem + 64 * 256 * 4);       // [al][66]
    float*  sE     = (float*)(bsmem + 64 * 256 * 4);        // alias in T
    float*  sStats = (float*)(bsmem + 64 * 256 * 4 + 64 * 66 * 8);

    const int t = threadIdx.x;
    const int b = blockIdx.x;
    const int fy = blockIdx.y;
    const int w = t >> 5, l = t & 31;
    const float* act_b = actions + (size_t)b * N_ * A_;

    // load actions transposed + dup: sActT2[al][n]
#pragma unroll
    for (int j = 0; j < 16; j++) {
        int i = t + j * 256;
        int n = i >> 6, al = i & 63;
        float v = act_b[i];
        sActT2[al * 66 + n] = make_float2(v, v);
    }
    __syncthreads();

    // ---- LN stats per n (closed form) ----
    {
        const int n = t >> 2, seg = t & 3;
        float dotj[16];
#pragma unroll
        for (int j = 0; j < 16; j++) dotj[j] = 0.f;
        for (int al = 0; al < 64; al++) {
            float av = sActT2[al * 66 + n].x;
            const float4* g4 = (const float4*)&g_G2[al * 64 + seg * 16];
#pragma unroll
            for (int q = 0; q < 4; q++) {
                float4 g = g4[q];
                dotj[q * 4 + 0] += av * g.x;
                dotj[q * 4 + 1] += av * g.y;
                dotj[q * 4 + 2] += av * g.z;
                dotj[q * 4 + 3] += av * g.w;
            }
        }
        float quad = 0.f, wbp = 0.f, wsp = 0.f;
#pragma unroll
        for (int j = 0; j < 16; j++) {
            int be = seg * 16 + j;
            float ab = sActT2[be * 66 + n].x;
            quad += ab * dotj[j];
            wbp += ab * g_wb[be];
            wsp += ab * g_wsum[be];
        }
#pragma unroll
        for (int o = 1; o < 4; o <<= 1) {
            quad += __shfl_xor_sync(0xffffffffu, quad, o);
            wbp  += __shfl_xor_sync(0xffffffffu, wbp, o);
            wsp  += __shfl_xor_sync(0xffffffffu, wsp, o);
        }
        if (seg == 0) {
            float bb = g_scal[0], sb = g_scal[1];
            float mu = (wsp + sb) * (1.f / 512.f);
            float e2 = (quad + 2.f * wbp + bb) * (1.f / 512.f);
            float var = e2 - mu * mu;
            sStats[2 * n]     = mu;
            sStats[2 * n + 1] = rsqrtf(var + 1e-5f);
        }
    }
    __syncthreads();

    const int fbase = fy * 256 + l * 8;   // 8 global f cols per lane
    const int n0 = w * 8;                 // P: warp's 8 n rows

    // ---- Phase P: v[n][f] = rs*(act@M1 + c1) - rs*mu*c2 + c3 -> sV ----
    {
        u64 acc[8][4];
        ulonglong2 c1a = *(const ulonglong2*)&g_c1[fbase];
        ulonglong2 c1b = *(const ulonglong2*)&g_c1[fbase + 4];
#pragma unroll
        for (int n = 0; n < 8; n++) {
            acc[n][0] = c1a.x; acc[n][1] = c1a.y;
            acc[n][2] = c1b.x; acc[n][3] = c1b.y;
        }
#pragma unroll 2
        for (int al = 0; al < 64; al++) {
            ulonglong2 w01 = *(const ulonglong2*)&g_M1[al * 512 + fbase];
            ulonglong2 w23 = *(const ulonglong2*)&g_M1[al * 512 + fbase + 4];
            ulonglong2 aA = *(const ulonglong2*)&sActT2[al * 66 + n0];      // n0,n0+1
            ulonglong2 aB = *(const ulonglong2*)&sActT2[al * 66 + n0 + 2];
            ulonglong2 aC = *(const ulonglong2*)&sActT2[al * 66 + n0 + 4];
            ulonglong2 aD = *(const ulonglong2*)&sActT2[al * 66 + n0 + 6];
            u64 dn[8] = {aA.x, aA.y, aB.x, aB.y, aC.x, aC.y, aD.x, aD.y};
#pragma unroll
            for (int n = 0; n < 8; n++) {
                acc[n][0] = fma2(dn[n], w01.x, acc[n][0]);
                acc[n][1] = fma2(dn[n], w01.y, acc[n][1]);
                acc[n][2] = fma2(dn[n], w23.x, acc[n][2]);
                acc[n][3] = fma2(dn[n], w23.y, acc[n][3]);
            }
        }
        ulonglong2 c2a = *(const ulonglong2*)&g_c2[fbase];
        ulonglong2 c2b = *(const ulonglong2*)&g_c2[fbase + 4];
        ulonglong2 c3a = *(const ulonglong2*)&g_c3[fbase];
        ulonglong2 c3b = *(const ulonglong2*)&g_c3[fbase + 4];
#pragma unroll
        for (int n = 0; n < 8; n++) {
            float mu = sStats[2 * (n0 + n)], rs = sStats[2 * (n0 + n) + 1];
            u64 R = dup2(rs), M = dup2(-rs * mu);
            ulonglong2 o0, o1;
            o0.x = fma2(R, acc[n][0], fma2(M, c2a.x, c3a.x));
            o0.y = fma2(R, acc[n][1], fma2(M, c2a.y, c3a.y));
            o1.x = fma2(R, acc[n][2], fma2(M, c2b.x, c3b.x));
            o1.y = fma2(R, acc[n][3], fma2(M, c2b.y, c3b.y));
            *(ulonglong2*)&sV[(n0 + n) * 256 + l * 8]     = o0;
            *(ulonglong2*)&sV[(n0 + n) * 256 + l * 8 + 4] = o1;
        }
    }
    __syncthreads();

    // ---- stage all of E (dup pairs) into the dead act region ----
    {
        const float4* gE4 = (const float4*)(g_attnE2 + (size_t)b * 8192);
        float4* sE4 = (float4*)sE;
#pragma unroll
        for (int j = 0; j < 8; j++)
            sE4[t + j * 256] = gE4[t + j * 256];
    }
    __syncthreads();

    // ---- Phase T: out[s][f] = sum_n e(n,s) * v[n][f]; warp owns 8 s rows ----
    {
        const int s0 = w * 8;
        u64 acc[8][4];
#pragma unroll
        for (int i = 0; i < 8; i++)
#pragma unroll
            for (int p = 0; p < 4; p++) acc[i][p] = 0ull;

#pragma unroll 2
        for (int n = 0; n < 64; n++) {
            ulonglong2 v01 = *(const ulonglong2*)&sV[n * 256 + l * 8];
            ulonglong2 v23 = *(const ulonglong2*)&sV[n * 256 + l * 8 + 4];
            ulonglong2 e01 = *(const ulonglong2*)&sE[n * 128 + s0 * 2];       // s0,s0+1
            ulonglong2 e23 = *(const ulonglong2*)&sE[n * 128 + s0 * 2 + 4];
            ulonglong2 e45 = *(const ulonglong2*)&sE[n * 128 + s0 * 2 + 8];
            ulonglong2 e67 = *(const ulonglong2*)&sE[n * 128 + s0 * 2 + 12];
            u64 es[8] = {e01.x, e01.y, e23.x, e23.y, e45.x, e45.y, e67.x, e67.y};
#pragma unroll
            for (int i = 0; i < 8; i++) {
                acc[i][0] = fma2(es[i], v01.x, acc[i][0]);
                acc[i][1] = fma2(es[i], v01.y, acc[i][1]);
                acc[i][2] = fma2(es[i], v23.x, acc[i][2]);
                acc[i][3] = fma2(es[i], v23.y, acc[i][3]);
            }
        }
        float* o1 = out_slots + (size_t)b * S_ * F_;
#pragma unroll
        for (int i = 0; i < 8; i++) {
            float2 p0 = unpk(acc[i][0]), p1 = unpk(acc[i][1]);
            float2 p2 = unpk(acc[i][2]), p3 = unpk(acc[i][3]);
            float* dst = o1 + (s0 + i) * 512 + fbase;
            *(float4*)dst       = make_float4(p0.x, p0.y, p1.x, p1.y);
            *(float4*)(dst + 4) = make_float4(p2.x, p2.y, p3.x, p3.y);
        }
    }
}

// ---------------- launch ----------------------------------------------------------
extern "C" void kernel_launch(void* const* d_in, const int* in_sizes, int n_in,
                              void* d_out, int out_size) {
    const float* slots   = (const float*)d_in[0];
    const float* actions = (const float*)d_in[1];
    const float* W_ae    = (const float*)d_in[2];
    const float* b_ae    = (const float*)d_in[3];
    const float* W_ie    = (const float*)d_in[4];
    const float* b_ie    = (const float*)d_in[5];
    const float* ln_g    = (const float*)d_in[6];
    const float* ln_b    = (const float*)d_in[7];
    const float* Wq      = (const float*)d_in[8];
    const float* Wk      = (const float*)d_in[9];
    const float* Wv      = (const float*)d_in[10];

    float* out      = (float*)d_out;
    float* out_attn = out + (size_t)B_ * S_ * F_;

    setup_master<<<138, 512>>>(W_ae, b_ae, W_ie, b_ie, ln_g, ln_b, Wk, Wv);
    setup_kq<<<dim3(8, 8), 64>>>(Wq);

    cudaFuncSetAttribute(attn_kernel,
                         cudaFuncAttributeMaxDynamicSharedMemorySize, ASM_BYTES);
    attn_kernel<<<B_, 128, ASM_BYTES>>>(slots, out_attn);

    cudaFuncSetAttribute(bind_kernel,
                         cudaFuncAttributeMaxDynamicSharedMemorySize, BSM_BYTES);
    bind_kernel<<<dim3(B_, 2), 256, BSM_BYTES>>>(actions, out);
}

// round 9
// speedup vs baseline: 1.2334x; 1.0190x over previous
#include <cuda_runtime.h>
#include <cstdint>

#define B_ 2048
#define S_ 64
#define D_ 512
#define N_ 64
#define A_ 64
#define F_ 512

typedef unsigned long long u64;

// ---------------- persistent device scratch ------------------------------------
__device__ __align__(16) float g_k[N_ * F_];
__device__ __align__(16) u64   g_kqD[(size_t)D_ * N_];   // dup pairs [d][n], 256KB
__device__ __align__(16) float g_M1[A_ * F_];
__device__ __align__(16) float g_c1[F_];
__device__ __align__(16) float g_c2[F_];
__device__ __align__(16) float g_c3[F_];
__device__ __align__(16) float g_G2[A_ * A_];
__device__ __align__(16) float g_wb[A_];
__device__ __align__(16) float g_wsum[A_];
__device__ __align__(16) float g_scal[2];
__device__ __align__(16) float g_attnE2[(size_t)B_ * N_ * S_ * 2];  // dup pairs

// ---------------- f32x2 helpers --------------------------------------------------
__device__ __forceinline__ u64 fma2(u64 a, u64 b, u64 c) {
    u64 d;
    asm("fma.rn.f32x2 %0, %1, %2, %3;" : "=l"(d) : "l"(a), "l"(b), "l"(c));
    return d;
}
__device__ __forceinline__ u64 dup2(float v) {
    u64 d;
    asm("mov.b64 %0, {%1, %1};" : "=l"(d) : "f"(v));
    return d;
}
__device__ __forceinline__ float2 unpk(u64 v) {
    float2 r;
    asm("mov.b64 {%0, %1}, %2;" : "=f"(r.x), "=f"(r.y) : "l"(v));
    return r;
}

// ---------------- setup: everything except kqD, from raw inputs -------------------
__global__ __launch_bounds__(512)
void setup_master(const float* __restrict__ W_ae, const float* __restrict__ b_ae,
                  const float* __restrict__ W_ie, const float* __restrict__ b_ie,
                  const float* __restrict__ ln_g, const float* __restrict__ ln_b,
                  const float* __restrict__ Wk, const float* __restrict__ Wv) {
    const int t = threadIdx.x;
    const int b = blockIdx.x;
    if (b < 64) {
        float a0 = 0.f, a1 = 0.f, a2 = 0.f, a3 = 0.f;
        for (int f = 0; f < F_; f += 4) {
            float4 wv = *(const float4*)&Wv[t * 512 + f];
            float4 lg = *(const float4*)&ln_g[f];
            a0 += W_ae[(f + 0) * A_ + b] * lg.x * wv.x;
            a1 += W_ae[(f + 1) * A_ + b] * lg.y * wv.y;
            a2 += W_ae[(f + 2) * A_ + b] * lg.z * wv.z;
            a3 += W_ae[(f + 3) * A_ + b] * lg.w * wv.w;
        }
        g_M1[b * 512 + t] = (a0 + a1) + (a2 + a3);
    } else if (b == 64) {
        float c1 = 0.f, c2 = 0.f, c3 = 0.f;
        for (int f = 0; f < F_; f += 2) {
            float2 wv = *(const float2*)&Wv[t * 512 + f];
            c1 += b_ae[f] * ln_g[f] * wv.x + b_ae[f + 1] * ln_g[f + 1] * wv.y;
            c2 += ln_g[f] * wv.x + ln_g[f + 1] * wv.y;
            c3 += ln_b[f] * wv.x + ln_b[f + 1] * wv.y;
        }
        g_c1[t] = c1; g_c2[t] = c2; g_c3[t] = c3;
    } else if (b < 73) {
        int idx = (b - 65) * 512 + t;
        int al = idx & 63, be = idx >> 6;
        float a0 = 0.f, a1 = 0.f, a2 = 0.f, a3 = 0.f;
#pragma unroll 4
        for (int f = 0; f < F_; f += 4) {
            a0 += W_ae[(f + 0) * A_ + al] * W_ae[(f + 0) * A_ + be];
            a1 += W_ae[(f + 1) * A_ + al] * W_ae[(f + 1) * A_ + be];
            a2 += W_ae[(f + 2) * A_ + al] * W_ae[(f + 2) * A_ + be];
            a3 += W_ae[(f + 3) * A_ + al] * W_ae[(f + 3) * A_ + be];
        }
        g_G2[al * A_ + be] = (a0 + a1) + (a2 + a3);
    } else if (b == 73) {
        if (t < 64) {
            float aw = 0.f, as = 0.f;
#pragma unroll 4
            for (int f = 0; f < F_; f++) {
                float w = W_ae[f * A_ + t];
                aw += w * b_ae[f];
                as += w;
            }
            g_wb[t] = aw;
            g_wsum[t] = as;
        } else if (t == 64) {
            float bb = 0.f, sb = 0.f;
            for (int f = 0; f < F_; f++) {
                float v = b_ae[f];
                bb += v * v;
                sb += v;
            }
            g_scal[0] = bb;
            g_scal[1] = sb;
        }
    } else {
        int idx = (b - 74) * 512 + t;
        int n = idx & 63;
        int g = idx >> 6;
        float a0 = 0.f, a1 = 0.f, a2 = 0.f, a3 = 0.f;
#pragma unroll 4
        for (int f = 0; f < F_; f += 4) {
            a0 += (W_ie[(f + 0) * N_ + n] + b_ie[f + 0]) * Wk[g * F_ + f + 0];
            a1 += (W_ie[(f + 1) * N_ + n] + b_ie[f + 1]) * Wk[g * F_ + f + 1];
            a2 += (W_ie[(f + 2) * N_ + n] + b_ie[f + 2]) * Wk[g * F_ + f + 2];
            a3 += (W_ie[(f + 3) * N_ + n] + b_ie[f + 3]) * Wk[g * F_ + f + 3];
        }
        g_k[n * F_ + g] = (a0 + a1) + (a2 + a3);
    }
}

// ---------------- setup 2: kqD[d][n] = dup(scale * (k @ Wq)[n][d]) ----------------
__global__ void setup_kq(const float* __restrict__ Wq) {
    int d = blockIdx.y * 64 + threadIdx.x;
    int n0 = blockIdx.x * 8;
    float acc[8];
#pragma unroll
    for (int j = 0; j < 8; j++) acc[j] = 0.f;
#pragma unroll 4
    for (int f = 0; f < F_; f++) {
        float wq = Wq[f * D_ + d];
#pragma unroll
        for (int j = 0; j < 8; j++)
            acc[j] += g_k[(n0 + j) * F_ + f] * wq;
    }
    const float scale = 0.04419417382415922f;  // 512^-0.5
#pragma unroll
    for (int j = 0; j < 8; j++)
        g_kqD[(size_t)d * 64 + n0 + j] = dup2(acc[j] * scale);
}

// =================== kernel A v3: logits + softmax ===============================
// 128 threads: nI = t>>3 (16 groups of 4 n), sI = t&7.
// Per-thread tile: 4 n x 8 s (s = 4sI..4sI+3 and 32+4sI..+3).
// slots staged transposed with XOR-16B swizzle, stride 68; kq from g_kqD (LDG).
__global__ __launch_bounds__(128, 5)
void attn_kernel(const float* __restrict__ slots, float* __restrict__ out_attn) {
    __shared__ float sSlT[64 * 68];     // 17.4KB
    const int t = threadIdx.x;
    const int b = blockIdx.x;
    const float* slots_b = slots + (size_t)b * S_ * D_;
    const int nI = t >> 3, sI = t & 7;

    u64 acc[4][4];
#pragma unroll
    for (int i = 0; i < 4; i++)
#pragma unroll
        for (int p = 0; p < 4; p++) acc[i][p] = 0ull;

    for (int dc = 0; dc < 8; dc++) {
        if (dc) __syncthreads();
        // stage slots chunk: logical [d][s], swizzled col16 = (s>>2) ^ (d&15)
#pragma unroll
        for (int j = 0; j < 8; j++) {
            int idx = t + j * 128;
            int s = idx >> 4, q = idx & 15;
            float4 v = *(const float4*)&slots_b[s * 512 + dc * 64 + q * 4];
            int sh = s >> 2, slo = s & 3;
            float vv[4] = {v.x, v.y, v.z, v.w};
#pragma unroll
            for (int k = 0; k < 4; k++) {
                int d = q * 4 + k;
                sSlT[d * 68 + (((sh ^ (d & 15)) << 2) | slo)] = vv[k];
            }
        }
        __syncthreads();

#pragma unroll 4
        for (int d = 0; d < 64; d++) {
            int dg = dc * 64 + d;
            ulonglong2 kA = *(const ulonglong2*)&g_kqD[(size_t)dg * 64 + 4 * nI];
            ulonglong2 kB = *(const ulonglong2*)&g_kqD[(size_t)dg * 64 + 4 * nI + 2];
            int dx = d & 15;
            ulonglong2 sA = *(const ulonglong2*)&sSlT[d * 68 + ((sI ^ dx) << 2)];
            ulonglong2 sB = *(const ulonglong2*)&sSlT[d * 68 + (((8 + sI) ^ dx) << 2)];
            acc[0][0] = fma2(kA.x, sA.x, acc[0][0]);
            acc[0][1] = fma2(kA.x, sA.y, acc[0][1]);
            acc[0][2] = fma2(kA.x, sB.x, acc[0][2]);
            acc[0][3] = fma2(kA.x, sB.y, acc[0][3]);
            acc[1][0] = fma2(kA.y, sA.x, acc[1][0]);
            acc[1][1] = fma2(kA.y, sA.y, acc[1][1]);
            acc[1][2] = fma2(kA.y, sB.x, acc[1][2]);
            acc[1][3] = fma2(kA.y, sB.y, acc[1][3]);
            acc[2][0] = fma2(kB.x, sA.x, acc[2][0]);
            acc[2][1] = fma2(kB.x, sA.y, acc[2][1]);
            acc[2][2] = fma2(kB.x, sB.x, acc[2][2]);
            acc[2][3] = fma2(kB.x, sB.y, acc[2][3]);
            acc[3][0] = fma2(kB.y, sA.x, acc[3][0]);
            acc[3][1] = fma2(kB.y, sA.y, acc[3][1]);
            acc[3][2] = fma2(kB.y, sB.x, acc[3][2]);
            acc[3][3] = fma2(kB.y, sB.y, acc[3][3]);
        }
    }

    // register softmax: 8 lanes (sI) per n-row; l[0..3]=s 4sI.., l[4..7]=32+4sI..
    float* o2 = out_attn + (size_t)b * N_ * S_;
    float* gE = g_attnE2 + (size_t)b * 8192;
#pragma unroll
    for (int i = 0; i < 4; i++) {
        float l[8];
#pragma unroll
        for (int p = 0; p < 4; p++) {
            float2 q = unpk(acc[i][p]);
            l[2 * p] = q.x;
            l[2 * p + 1] = q.y;
        }
        float m = l[0];
#pragma unroll
        for (int j = 1; j < 8; j++) m = fmaxf(m, l[j]);
#pragma unroll
        for (int o = 1; o < 8; o <<= 1) m = fmaxf(m, __shfl_xor_sync(0xffffffffu, m, o));
        float sum = 0.f;
#pragma unroll
        for (int j = 0; j < 8; j++) {
            l[j] = __expf(l[j] - m);
            sum += l[j];
        }
#pragma unroll
        for (int o = 1; o < 8; o <<= 1) sum += __shfl_xor_sync(0xffffffffu, sum, o);
        float inv = 1.f / sum;
#pragma unroll
        for (int j = 0; j < 8; j++) l[j] *= inv;

        int n = nI * 4 + i;
        *(float4*)&o2[n * 64 + 4 * sI]      = make_float4(l[0], l[1], l[2], l[3]);
        *(float4*)&o2[n * 64 + 32 + 4 * sI] = make_float4(l[4], l[5], l[6], l[7]);
        float4* gdA = (float4*)&gE[n * 128 + 8 * sI];
        gdA[0] = make_float4(l[0] + 1e-8f, l[0] + 1e-8f, l[1] + 1e-8f, l[1] + 1e-8f);
        gdA[1] = make_float4(l[2] + 1e-8f, l[2] + 1e-8f, l[3] + 1e-8f, l[3] + 1e-8f);
        float4* gdB = (float4*)&gE[n * 128 + 64 + 8 * sI];
        gdB[0] = make_float4(l[4] + 1e-8f, l[4] + 1e-8f, l[5] + 1e-8f, l[5] + 1e-8f);
        gdB[1] = make_float4(l[6] + 1e-8f, l[6] + 1e-8f, l[7] + 1e-8f, l[7] + 1e-8f);
    }
}

// =================== kernel B v3: stats + P + T (dense f layout) ==================
// 256 threads, grid (2048, 2). warp w, lane l → f cols {l*4..+3} and {128+l*4..+3}.
#define BSM_BYTES (64 * 256 * 4 + 64 * 66 * 8 + 512)
__global__ __launch_bounds__(256, 2)
void bind_kernel(const float* __restrict__ actions,
                 float* __restrict__ out_slots) {
    extern __shared__ char bsmem[];
    float*  sV     = (float*)bsmem;                         // [n][256]
    float2* sActT2 = (float2*)(bsmem + 64 * 256 * 4);       // [al][66] dup
    float*  sE     = (float*)(bsmem + 64 * 256 * 4);        // alias in T
    float*  sStats = (float*)(bsmem + 64 * 256 * 4 + 64 * 66 * 8);

    const int t = threadIdx.x;
    const int b = blockIdx.x;
    const int fy = blockIdx.y;
    const int w = t >> 5, l = t & 31;
    const float* act_b = actions + (size_t)b * N_ * A_;

#pragma unroll
    for (int j = 0; j < 16; j++) {
        int i = t + j * 256;
        int n = i >> 6, al = i & 63;
        float v = act_b[i];
        sActT2[al * 66 + n] = make_float2(v, v);
    }
    __syncthreads();

    // ---- LN stats per n (closed form) ----
    {
        const int n = t >> 2, seg = t & 3;
        float dotj[16];
#pragma unroll
        for (int j = 0; j < 16; j++) dotj[j] = 0.f;
        for (int al = 0; al < 64; al++) {
            float av = sActT2[al * 66 + n].x;
            const float4* g4 = (const float4*)&g_G2[al * 64 + seg * 16];
#pragma unroll
            for (int q = 0; q < 4; q++) {
                float4 g = g4[q];
                dotj[q * 4 + 0] += av * g.x;
                dotj[q * 4 + 1] += av * g.y;
                dotj[q * 4 + 2] += av * g.z;
                dotj[q * 4 + 3] += av * g.w;
            }
        }
        float quad = 0.f, wbp = 0.f, wsp = 0.f;
#pragma unroll
        for (int j = 0; j < 16; j++) {
            int be = seg * 16 + j;
            float ab = sActT2[be * 66 + n].x;
            quad += ab * dotj[j];
            wbp += ab * g_wb[be];
            wsp += ab * g_wsum[be];
        }
#pragma unroll
        for (int o = 1; o < 4; o <<= 1) {
            quad += __shfl_xor_sync(0xffffffffu, quad, o);
            wbp  += __shfl_xor_sync(0xffffffffu, wbp, o);
            wsp  += __shfl_xor_sync(0xffffffffu, wsp, o);
        }
        if (seg == 0) {
            float bb = g_scal[0], sb = g_scal[1];
            float mu = (wsp + sb) * (1.f / 512.f);
            float e2 = (quad + 2.f * wbp + bb) * (1.f / 512.f);
            float var = e2 - mu * mu;
            sStats[2 * n]     = mu;
            sStats[2 * n + 1] = rsqrtf(var + 1e-5f);
        }
    }
    __syncthreads();

    const int fa = fy * 256 + l * 4;        // dense chunk A
    const int fb = fa + 128;                // dense chunk B
    const int n0 = w * 8;

    // ---- Phase P: v[n][f] -> sV ----
    {
        u64 acc[8][4];
        ulonglong2 c1a = *(const ulonglong2*)&g_c1[fa];
        ulonglong2 c1b = *(const ulonglong2*)&g_c1[fb];
#pragma unroll
        for (int n = 0; n < 8; n++) {
            acc[n][0] = c1a.x; acc[n][1] = c1a.y;
            acc[n][2] = c1b.x; acc[n][3] = c1b.y;
        }
#pragma unroll 2
        for (int al = 0; al < 64; al++) {
            ulonglong2 wa = *(const ulonglong2*)&g_M1[al * 512 + fa];
            ulonglong2 wb = *(const ulonglong2*)&g_M1[al * 512 + fb];
            ulonglong2 aA = *(const ulonglong2*)&sActT2[al * 66 + n0];
            ulonglong2 aB = *(const ulonglong2*)&sActT2[al * 66 + n0 + 2];
            ulonglong2 aC = *(const ulonglong2*)&sActT2[al * 66 + n0 + 4];
            ulonglong2 aD = *(const ulonglong2*)&sActT2[al * 66 + n0 + 6];
            u64 dn[8] = {aA.x, aA.y, aB.x, aB.y, aC.x, aC.y, aD.x, aD.y};
#pragma unroll
            for (int n = 0; n < 8; n++) {
                acc[n][0] = fma2(dn[n], wa.x, acc[n][0]);
                acc[n][1] = fma2(dn[n], wa.y, acc[n][1]);
                acc[n][2] = fma2(dn[n], wb.x, acc[n][2]);
                acc[n][3] = fma2(dn[n], wb.y, acc[n][3]);
            }
        }
        ulonglong2 c2a = *(const ulonglong2*)&g_c2[fa];
        ulonglong2 c2b = *(const ulonglong2*)&g_c2[fb];
        ulonglong2 c3a = *(const ulonglong2*)&g_c3[fa];
        ulonglong2 c3b = *(const ulonglong2*)&g_c3[fb];
#pragma unroll
        for (int n = 0; n < 8; n++) {
            float mu = sStats[2 * (n0 + n)], rs = sStats[2 * (n0 + n) + 1];
            u64 R = dup2(rs), M = dup2(-rs * mu);
            ulonglong2 o0, o1;
            o0.x = fma2(R, acc[n][0], fma2(M, c2a.x, c3a.x));
            o0.y = fma2(R, acc[n][1], fma2(M, c2a.y, c3a.y));
            o1.x = fma2(R, acc[n][2], fma2(M, c2b.x, c3b.x));
            o1.y = fma2(R, acc[n][3], fma2(M, c2b.y, c3b.y));
            *(ulonglong2*)&sV[(n0 + n) * 256 + l * 4]       = o0;
            *(ulonglong2*)&sV[(n0 + n) * 256 + 128 + l * 4] = o1;
        }
    }
    __syncthreads();

    // ---- stage all of E (dup pairs) into the dead act region ----
    {
        const float4* gE4 = (const float4*)(g_attnE2 + (size_t)b * 8192);
        float4* sE4 = (float4*)sE;
#pragma unroll
        for (int j = 0; j < 8; j++)
            sE4[t + j * 256] = gE4[t + j * 256];
    }
    __syncthreads();

    // ---- Phase T: out[s][f] = sum_n e(n,s) * v[n][f]; warp owns s0..s0+7 ----
    {
        const int s0 = w * 8;
        u64 acc[8][4];
#pragma unroll
        for (int i = 0; i < 8; i++)
#pragma unroll
            for (int p = 0; p < 4; p++) acc[i][p] = 0ull;

#pragma unroll 2
        for (int n = 0; n < 64; n++) {
            ulonglong2 va = *(const ulonglong2*)&sV[n * 256 + l * 4];
            ulonglong2 vb = *(const ulonglong2*)&sV[n * 256 + 128 + l * 4];
            ulonglong2 e01 = *(const ulonglong2*)&sE[n * 128 + s0 * 2];
            ulonglong2 e23 = *(const ulonglong2*)&sE[n * 128 + s0 * 2 + 4];
            ulonglong2 e45 = *(const ulonglong2*)&sE[n * 128 + s0 * 2 + 8];
            ulonglong2 e67 = *(const ulonglong2*)&sE[n * 128 + s0 * 2 + 12];
            u64 es[8] = {e01.x, e01.y, e23.x, e23.y, e45.x, e45.y, e67.x, e67.y};
#pragma unroll
            for (int i = 0; i < 8; i++) {
                acc[i][0] = fma2(es[i], va.x, acc[i][0]);
                acc[i][1] = fma2(es[i], va.y, acc[i][1]);
                acc[i][2] = fma2(es[i], vb.x, acc[i][2]);
                acc[i][3] = fma2(es[i], vb.y, acc[i][3]);
            }
        }
        float* o1 = out_slots + (size_t)b * S_ * F_ + fy * 256;
#pragma unroll
        for (int i = 0; i < 8; i++) {
            float2 p0 = unpk(acc[i][0]), p1 = unpk(acc[i][1]);
            float2 p2 = unpk(acc[i][2]), p3 = unpk(acc[i][3]);
            float* dst = o1 + (s0 + i) * 512 + l * 4;
            *(float4*)dst         = make_float4(p0.x, p0.y, p1.x, p1.y);
            *(float4*)(dst + 128) = make_float4(p2.x, p2.y, p3.x, p3.y);
        }
    }
}

// ---------------- launch ----------------------------------------------------------
extern "C" void kernel_launch(void* const* d_in, const int* in_sizes, int n_in,
                              void* d_out, int out_size) {
    const float* slots   = (const float*)d_in[0];
    const float* actions = (const float*)d_in[1];
    const float* W_ae    = (const float*)d_in[2];
    const float* b_ae    = (const float*)d_in[3];
    const float* W_ie    = (const float*)d_in[4];
    const float* b_ie    = (const float*)d_in[5];
    const float* ln_g    = (const float*)d_in[6];
    const float* ln_b    = (const float*)d_in[7];
    const float* Wq      = (const float*)d_in[8];
    const float* Wk      = (const float*)d_in[9];
    const float* Wv      = (const float*)d_in[10];

    float* out      = (float*)d_out;
    float* out_attn = out + (size_t)B_ * S_ * F_;

    setup_master<<<138, 512>>>(W_ae, b_ae, W_ie, b_ie, ln_g, ln_b, Wk, Wv);
    setup_kq<<<dim3(8, 8), 64>>>(Wq);

    attn_kernel<<<B_, 128>>>(slots, out_attn);

    cudaFuncSetAttribute(bind_kernel,
                         cudaFuncAttributeMaxDynamicSharedMemorySize, BSM_BYTES);
    bind_kernel<<<dim3(B_, 2), 256, BSM_BYTES>>>(actions, out);
}

// round 10
// speedup vs baseline: 1.3046x; 1.0578x over previous
#include <cuda_runtime.h>
#include <cstdint>

#define B_ 2048
#define S_ 64
#define D_ 512
#define N_ 64
#define A_ 64
#define F_ 512

typedef unsigned long long u64;

// ---------------- persistent device scratch ------------------------------------
__device__ __align__(16) float g_k[N_ * F_];
__device__ __align__(16) u64   g_kqD[(size_t)D_ * N_];     // dup pairs [d][n]
__device__ __align__(16) float g_M1e[68 * F_];             // rows 0..63 M1, 64 c1, 65 c2, 66 c3
__device__ __align__(16) float g_G2[A_ * A_];
__device__ __align__(16) float g_wb[A_];
__device__ __align__(16) float g_wsum[A_];
__device__ __align__(16) float g_scal[2];
__device__ __align__(16) float g_QeT[(size_t)B_ * 68 * 128];  // dup pairs [b][k][2s]

// ---------------- f32x2 helpers --------------------------------------------------
__device__ __forceinline__ u64 fma2(u64 a, u64 b, u64 c) {
    u64 d;
    asm("fma.rn.f32x2 %0, %1, %2, %3;" : "=l"(d) : "l"(a), "l"(b), "l"(c));
    return d;
}
__device__ __forceinline__ u64 dup2(float v) {
    u64 d;
    asm("mov.b64 %0, {%1, %1};" : "=l"(d) : "f"(v));
    return d;
}
__device__ __forceinline__ float2 unpk(u64 v) {
    float2 r;
    asm("mov.b64 {%0, %1}, %2;" : "=f"(r.x), "=f"(r.y) : "l"(v));
    return r;
}

// ---------------- setup: M1e, G2, scalars, k -------------------------------------
__global__ __launch_bounds__(512)
void setup_master(const float* __restrict__ W_ae, const float* __restrict__ b_ae,
                  const float* __restrict__ W_ie, const float* __restrict__ b_ie,
                  const float* __restrict__ ln_g, const float* __restrict__ ln_b,
                  const float* __restrict__ Wk, const float* __restrict__ Wv) {
    const int t = threadIdx.x;
    const int b = blockIdx.x;
    if (b < 64) {
        float a0 = 0.f, a1 = 0.f, a2 = 0.f, a3 = 0.f;
        for (int f = 0; f < F_; f += 4) {
            float4 wv = *(const float4*)&Wv[t * 512 + f];
            float4 lg = *(const float4*)&ln_g[f];
            a0 += W_ae[(f + 0) * A_ + b] * lg.x * wv.x;
            a1 += W_ae[(f + 1) * A_ + b] * lg.y * wv.y;
            a2 += W_ae[(f + 2) * A_ + b] * lg.z * wv.z;
            a3 += W_ae[(f + 3) * A_ + b] * lg.w * wv.w;
        }
        g_M1e[b * 512 + t] = (a0 + a1) + (a2 + a3);
    } else if (b == 64) {
        float c1 = 0.f, c2 = 0.f, c3 = 0.f;
        for (int f = 0; f < F_; f += 2) {
            float2 wv = *(const float2*)&Wv[t * 512 + f];
            c1 += b_ae[f] * ln_g[f] * wv.x + b_ae[f + 1] * ln_g[f + 1] * wv.y;
            c2 += ln_g[f] * wv.x + ln_g[f + 1] * wv.y;
            c3 += ln_b[f] * wv.x + ln_b[f + 1] * wv.y;
        }
        g_M1e[64 * 512 + t] = c1;
        g_M1e[65 * 512 + t] = c2;
        g_M1e[66 * 512 + t] = c3;
        g_M1e[67 * 512 + t] = 0.f;
    } else if (b < 73) {
        int idx = (b - 65) * 512 + t;
        int al = idx & 63, be = idx >> 6;
        float a0 = 0.f, a1 = 0.f, a2 = 0.f, a3 = 0.f;
#pragma unroll 4
        for (int f = 0; f < F_; f += 4) {
            a0 += W_ae[(f + 0) * A_ + al] * W_ae[(f + 0) * A_ + be];
            a1 += W_ae[(f + 1) * A_ + al] * W_ae[(f + 1) * A_ + be];
            a2 += W_ae[(f + 2) * A_ + al] * W_ae[(f + 2) * A_ + be];
            a3 += W_ae[(f + 3) * A_ + al] * W_ae[(f + 3) * A_ + be];
        }
        g_G2[al * A_ + be] = (a0 + a1) + (a2 + a3);
    } else if (b == 73) {
        if (t < 64) {
            float aw = 0.f, as = 0.f;
#pragma unroll 4
            for (int f = 0; f < F_; f++) {
                float w = W_ae[f * A_ + t];
                aw += w * b_ae[f];
                as += w;
            }
            g_wb[t] = aw;
            g_wsum[t] = as;
        } else if (t == 64) {
            float bb = 0.f, sb = 0.f;
            for (int f = 0; f < F_; f++) {
                float v = b_ae[f];
                bb += v * v;
                sb += v;
            }
            g_scal[0] = bb;
            g_scal[1] = sb;
        }
    } else {
        int idx = (b - 74) * 512 + t;
        int n = idx & 63;
        int g = idx >> 6;
        float a0 = 0.f, a1 = 0.f, a2 = 0.f, a3 = 0.f;
#pragma unroll 4
        for (int f = 0; f < F_; f += 4) {
            a0 += (W_ie[(f + 0) * N_ + n] + b_ie[f + 0]) * Wk[g * F_ + f + 0];
            a1 += (W_ie[(f + 1) * N_ + n] + b_ie[f + 1]) * Wk[g * F_ + f + 1];
            a2 += (W_ie[(f + 2) * N_ + n] + b_ie[f + 2]) * Wk[g * F_ + f + 2];
            a3 += (W_ie[(f + 3) * N_ + n] + b_ie[f + 3]) * Wk[g * F_ + f + 3];
        }
        g_k[n * F_ + g] = (a0 + a1) + (a2 + a3);
    }
}

// ---------------- setup 2: kqD[d][n] = dup(scale * (k @ Wq)[n][d]) ----------------
__global__ void setup_kq(const float* __restrict__ Wq) {
    int d = blockIdx.y * 64 + threadIdx.x;
    int n0 = blockIdx.x * 8;
    float acc[8];
#pragma unroll
    for (int j = 0; j < 8; j++) acc[j] = 0.f;
#pragma unroll 4
    for (int f = 0; f < F_; f++) {
        float wq = Wq[f * D_ + d];
#pragma unroll
        for (int j = 0; j < 8; j++)
            acc[j] += g_k[(n0 + j) * F_ + f] * wq;
    }
    const float scale = 0.04419417382415922f;  // 512^-0.5
#pragma unroll
    for (int j = 0; j < 8; j++)
        g_kqD[(size_t)d * 64 + n0 + j] = dup2(acc[j] * scale);
}

// =================== kernel A: logits + softmax + stats + Qe ======================
// 128 threads. smem (dynamic, 51.2KB):
//   [0)      sSlT  64x68 floats (phase L)  -- aliased by sActR 68x65 afterwards
//   [4420)   sAttn 64x64
//   [8516)   sAct  64x65
//   [12676)  sMu 64, sRs 64
#define AQ_SLT   0
#define AQ_ATTN  4420
#define AQ_ACT   (4420 + 4096)
#define AQ_MU    (4420 + 4096 + 4160)
#define AQ_RS    (AQ_MU + 64)
#define AQ_FLOATS (AQ_RS + 64)
__global__ __launch_bounds__(128)
void attnq_kernel(const float* __restrict__ slots,
                  const float* __restrict__ actions,
                  float* __restrict__ out_attn) {
    extern __shared__ float sq[];
    float* sSlT  = sq + AQ_SLT;      // [d][68] swizzled
    float* sActR = sq + AQ_SLT;      // [k][65] (after phase L)
    float* sAttn = sq + AQ_ATTN;     // [n][64]
    float* sAct  = sq + AQ_ACT;      // [n][65]
    float* sMu   = sq + AQ_MU;
    float* sRs   = sq + AQ_RS;

    const int t = threadIdx.x;
    const int b = blockIdx.x;
    const float* slots_b = slots + (size_t)b * S_ * D_;
    const float* act_b   = actions + (size_t)b * N_ * A_;
    const int nI = t >> 3, sI = t & 7;

    // load actions -> sAct [n][65]
#pragma unroll
    for (int j = 0; j < 32; j++) {
        int i = t + j * 128;
        sAct[(i >> 6) * 65 + (i & 63)] = act_b[i];
    }

    // ======== Phase L: logits (R9 scheme: swizzled slot transpose, kq LDG) ========
    u64 acc[4][4];
#pragma unroll
    for (int i = 0; i < 4; i++)
#pragma unroll
        for (int p = 0; p < 4; p++) acc[i][p] = 0ull;

    for (int dc = 0; dc < 8; dc++) {
        if (dc) __syncthreads();
#pragma unroll
        for (int j = 0; j < 8; j++) {
            int idx = t + j * 128;
            int s = idx >> 4, q = idx & 15;
            float4 v = *(const float4*)&slots_b[s * 512 + dc * 64 + q * 4];
            int sh = s >> 2, slo = s & 3;
            float vv[4] = {v.x, v.y, v.z, v.w};
#pragma unroll
            for (int k = 0; k < 4; k++) {
                int d = q * 4 + k;
                sSlT[d * 68 + (((sh ^ (d & 15)) << 2) | slo)] = vv[k];
            }
        }
        __syncthreads();

#pragma unroll 4
        for (int d = 0; d < 64; d++) {
            int dg = dc * 64 + d;
            ulonglong2 kA = *(const ulonglong2*)&g_kqD[(size_t)dg * 64 + 4 * nI];
            ulonglong2 kB = *(const ulonglong2*)&g_kqD[(size_t)dg * 64 + 4 * nI + 2];
            int dx = d & 15;
            ulonglong2 sA = *(const ulonglong2*)&sSlT[d * 68 + ((sI ^ dx) << 2)];
            ulonglong2 sB = *(const ulonglong2*)&sSlT[d * 68 + (((8 + sI) ^ dx) << 2)];
            acc[0][0] = fma2(kA.x, sA.x, acc[0][0]);
            acc[0][1] = fma2(kA.x, sA.y, acc[0][1]);
            acc[0][2] = fma2(kA.x, sB.x, acc[0][2]);
            acc[0][3] = fma2(kA.x, sB.y, acc[0][3]);
            acc[1][0] = fma2(kA.y, sA.x, acc[1][0]);
            acc[1][1] = fma2(kA.y, sA.y, acc[1][1]);
            acc[1][2] = fma2(kA.y, sB.x, acc[1][2]);
            acc[1][3] = fma2(kA.y, sB.y, acc[1][3]);
            acc[2][0] = fma2(kB.x, sA.x, acc[2][0]);
            acc[2][1] = fma2(kB.x, sA.y, acc[2][1]);
            acc[2][2] = fma2(kB.x, sB.x, acc[2][2]);
            acc[2][3] = fma2(kB.x, sB.y, acc[2][3]);
            acc[3][0] = fma2(kB.y, sA.x, acc[3][0]);
            acc[3][1] = fma2(kB.y, sA.y, acc[3][1]);
            acc[3][2] = fma2(kB.y, sB.x, acc[3][2]);
            acc[3][3] = fma2(kB.y, sB.y, acc[3][3]);
        }
    }
    __syncthreads();   // phase L fully done (sSlT free for sActR)

    // ======== softmax (8-lane register reduction), write out + sAttn ========
    float* o2 = out_attn + (size_t)b * N_ * S_;
#pragma unroll
    for (int i = 0; i < 4; i++) {
        float l[8];
#pragma unroll
        for (int p = 0; p < 4; p++) {
            float2 q = unpk(acc[i][p]);
            l[2 * p] = q.x;
            l[2 * p + 1] = q.y;
        }
        float m = l[0];
#pragma unroll
        for (int j = 1; j < 8; j++) m = fmaxf(m, l[j]);
#pragma unroll
        for (int o = 1; o < 8; o <<= 1) m = fmaxf(m, __shfl_xor_sync(0xffffffffu, m, o));
        float sum = 0.f;
#pragma unroll
        for (int j = 0; j < 8; j++) {
            l[j] = __expf(l[j] - m);
            sum += l[j];
        }
#pragma unroll
        for (int o = 1; o < 8; o <<= 1) sum += __shfl_xor_sync(0xffffffffu, sum, o);
        float inv = 1.f / sum;
#pragma unroll
        for (int j = 0; j < 8; j++) l[j] *= inv;

        int n = nI * 4 + i;
        float4 vA = make_float4(l[0], l[1], l[2], l[3]);
        float4 vB = make_float4(l[4], l[5], l[6], l[7]);
        *(float4*)&o2[n * 64 + 4 * sI]      = vA;
        *(float4*)&o2[n * 64 + 32 + 4 * sI] = vB;
        *(float4*)&sAttn[n * 64 + 4 * sI]      = vA;
        *(float4*)&sAttn[n * 64 + 32 + 4 * sI] = vB;
    }
    __syncthreads();

    // ======== LN stats per n: n = t>>1, seg = t&1 (32 beta cols) ========
    {
        const int n = t >> 1, seg = t & 1;
        float dotj[32];
#pragma unroll
        for (int j = 0; j < 32; j++) dotj[j] = 0.f;
        for (int al = 0; al < 64; al++) {
            float av = sAct[n * 65 + al];
            const float4* g4 = (const float4*)&g_G2[al * 64 + seg * 32];
#pragma unroll
            for (int q = 0; q < 8; q++) {
                float4 g = g4[q];
                dotj[q * 4 + 0] += av * g.x;
                dotj[q * 4 + 1] += av * g.y;
                dotj[q * 4 + 2] += av * g.z;
                dotj[q * 4 + 3] += av * g.w;
            }
        }
        float quad = 0.f, wbp = 0.f, wsp = 0.f;
#pragma unroll
        for (int j = 0; j < 32; j++) {
            int be = seg * 32 + j;
            float ab = sAct[n * 65 + be];
            quad += ab * dotj[j];
            wbp += ab * g_wb[be];
            wsp += ab * g_wsum[be];
        }
        quad += __shfl_xor_sync(0xffffffffu, quad, 1);
        wbp  += __shfl_xor_sync(0xffffffffu, wbp, 1);
        wsp  += __shfl_xor_sync(0xffffffffu, wsp, 1);
        if (seg == 0) {
            float bb = g_scal[0], sb = g_scal[1];
            float mu = (wsp + sb) * (1.f / 512.f);
            float e2 = (quad + 2.f * wbp + bb) * (1.f / 512.f);
            float var = e2 - mu * mu;
            sMu[n] = mu;
            sRs[n] = rsqrtf(var + 1e-5f);
        }
    }
    __syncthreads();

    // ======== actRaug -> sActR [k][65] (overwrites sSlT) ========
    {
        const int n = t >> 1, half = t & 1;
        float rs = sRs[n];
#pragma unroll
        for (int i = 0; i < 32; i++) {
            int al = half * 32 + i;
            sActR[al * 65 + n] = rs * sAct[n * 65 + al];
        }
        if (half == 0) {
            sActR[64 * 65 + n] = rs;
            sActR[65 * 65 + n] = -rs * sMu[n];
            sActR[66 * 65 + n] = 1.f;
        }
    }
    __syncthreads();

    // ======== Qe: QeT[k][s] = sum_n attn[n][s]*actRaug[n][k] + eps*colsum ========
    float* qdst_base = g_QeT + (size_t)b * 8704;
#pragma unroll
    for (int pass = 0; pass < 2; pass++) {
        int k = pass ? (64 + (t >> 1)) : (t >> 1);
        bool active = (pass == 0) || (t < 6);
        if (active) {
            const int shalf = t & 1;
            u64 qacc[16];
#pragma unroll
            for (int j = 0; j < 16; j++) qacc[j] = 0ull;
            float cs = 0.f;
            for (int n = 0; n < 64; n++) {
                float a = sActR[k * 65 + n];
                cs += a;
                u64 ad = dup2(a);
                const ulonglong2* ep =
                    (const ulonglong2*)&sAttn[n * 64 + shalf * 32];
#pragma unroll
                for (int jj = 0; jj < 8; jj++) {
                    ulonglong2 e = ep[jj];
                    qacc[2 * jj]     = fma2(ad, e.x, qacc[2 * jj]);
                    qacc[2 * jj + 1] = fma2(ad, e.y, qacc[2 * jj + 1]);
                }
            }
            u64 ec = dup2(cs * 1e-8f);
            u64 one = dup2(1.f);
            float* dst = qdst_base + k * 128 + shalf * 64;
#pragma unroll
            for (int j = 0; j < 16; j++) {
                qacc[j] = fma2(ec, one, qacc[j]);
                float2 p = unpk(qacc[j]);
                *(float4*)(dst + 4 * j) = make_float4(p.x, p.x, p.y, p.y);
            }
        }
    }
}

// =================== kernel B: out = Qe @ M1e (pure LDG GEMM, no smem) ===========
// grid (2048, 2), 256 threads. warp w -> s0 = 8w; lane l -> f = fy*256 + l*8.
__global__ __launch_bounds__(256, 2)
void out_kernel(float* __restrict__ out_slots) {
    const int t = threadIdx.x;
    const int b = blockIdx.x;
    const int fy = blockIdx.y;
    const int w = t >> 5, l = t & 31;
    const int s0 = w * 8;
    const int f = fy * 256 + l * 8;
    const float* Qb = g_QeT + (size_t)b * 8704;

    u64 acc[8][4];
#pragma unroll
    for (int i = 0; i < 8; i++)
#pragma unroll
        for (int p = 0; p < 4; p++) acc[i][p] = 0ull;

#pragma unroll 4
    for (int k = 0; k < 67; k++) {
        const ulonglong2* m = (const ulonglong2*)&g_M1e[k * 512 + f];
        ulonglong2 m0 = m[0], m1 = m[1];
        const ulonglong2* q = (const ulonglong2*)&Qb[k * 128 + 2 * s0];
        ulonglong2 q0 = q[0], q1 = q[1], q2 = q[2], q3 = q[3];
        u64 e[8] = {q0.x, q0.y, q1.x, q1.y, q2.x, q2.y, q3.x, q3.y};
#pragma unroll
        for (int i = 0; i < 8; i++) {
            acc[i][0] = fma2(e[i], m0.x, acc[i][0]);
            acc[i][1] = fma2(e[i], m0.y, acc[i][1]);
            acc[i][2] = fma2(e[i], m1.x, acc[i][2]);
            acc[i][3] = fma2(e[i], m1.y, acc[i][3]);
        }
    }

    float* o1 = out_slots + (size_t)b * S_ * F_ + f;
#pragma unroll
    for (int i = 0; i < 8; i++) {
        float2 p0 = unpk(acc[i][0]), p1 = unpk(acc[i][1]);
        float2 p2 = unpk(acc[i][2]), p3 = unpk(acc[i][3]);
        float* dst = o1 + (s0 + i) * 512;
        *(float4*)dst       = make_float4(p0.x, p0.y, p1.x, p1.y);
        *(float4*)(dst + 4) = make_float4(p2.x, p2.y, p3.x, p3.y);
    }
}

// ---------------- launch ----------------------------------------------------------
extern "C" void kernel_launch(void* const* d_in, const int* in_sizes, int n_in,
                              void* d_out, int out_size) {
    const float* slots   = (const float*)d_in[0];
    const float* actions = (const float*)d_in[1];
    const float* W_ae    = (const float*)d_in[2];
    const float* b_ae    = (const float*)d_in[3];
    const float* W_ie    = (const float*)d_in[4];
    const float* b_ie    = (const float*)d_in[5];
    const float* ln_g    = (const float*)d_in[6];
    const float* ln_b    = (const float*)d_in[7];
    const float* Wq      = (const float*)d_in[8];
    const float* Wk      = (const float*)d_in[9];
    const float* Wv      = (const float*)d_in[10];

    float* out      = (float*)d_out;
    float* out_attn = out + (size_t)B_ * S_ * F_;

    setup_master<<<138, 512>>>(W_ae, b_ae, W_ie, b_ie, ln_g, ln_b, Wk, Wv);
    setup_kq<<<dim3(8, 8), 64>>>(Wq);

    const size_t AQ_BYTES = AQ_FLOATS * sizeof(float);
    cudaFuncSetAttribute(attnq_kernel,
                         cudaFuncAttributeMaxDynamicSharedMemorySize, (int)AQ_BYTES);
    attnq_kernel<<<B_, 128, AQ_BYTES>>>(slots, actions, out_attn);

    out_kernel<<<dim3(B_, 2), 256>>>(out);
}